// round 12
// baseline (speedup 1.0000x reference)
#include <cuda_runtime.h>
#include <cuda_bf16.h>
#include <cstdint>

#define N_NODES  200000
#define N_EDGES  800000
#define N_GRAPHS 4096
#define MAXDEG   5
#define NBLK_SCAN 782   // ceil(N_NODES/256)
#define MAX_TILES 800   // ceil(N_NODES/256) + bucket remainders

// ---------------- scratch (static __device__, no allocs) ----------------
__device__ float g_pool[N_GRAPHS * 256];
__device__ float g_logit[N_NODES * 2];
__device__ float g_glogit[N_GRAPHS * 2];
__device__ float g_hf[N_NODES * 256];          // fp32 hidden state (agg input)
__device__ __nv_bfloat16 g_msg_hi[N_NODES * 256];
__device__ __nv_bfloat16 g_msg_lo[N_NODES * 256];
__device__ __nv_bfloat16 g_sa_hi[N_NODES * 256];
__device__ __nv_bfloat16 g_sa_lo[N_NODES * 256];
__device__ __nv_bfloat16 g_sb_hi[N_NODES * 256];
__device__ __nv_bfloat16 g_sb_lo[N_NODES * 256];
__device__ int   g_deg[N_NODES];
__device__ int   g_cur[N_NODES];
__device__ int   g_perm[N_NODES];
__device__ int   g_csr_off[N_NODES + 1];
__device__ int   g_csr[N_EDGES];
__device__ int   g_bsum[1024];
__device__ int   g_bpre[1024];
// [0..5] counts, [8..13] offsets, [16..21] cursors, [24..29] tile starts, [30] total tiles
__device__ int   g_meta[64];

// split-bf16 transposed weights: [d][n][k] K-major (k spans 2*CIN: Wl then Wr)
#define WOFF0 0
#define WOFF1 98304
#define WOFF2 294912
#define WOFF3 688128
#define WTOT  1474560
__device__ __nv_bfloat16 g_whi[WTOT];
__device__ __nv_bfloat16 g_wlo[WTOT];

// ---------------- helpers (portable PTX only) ----------------
__device__ __forceinline__ uint32_t smem_u32(const void* p) {
    uint32_t a;
    asm("{ .reg .u64 t; cvta.to.shared.u64 t, %1; cvt.u32.u64 %0, t; }" : "=r"(a) : "l"(p));
    return a;
}
__device__ __forceinline__ void red_add_v2(float* addr, float x, float y) {
    asm volatile("red.global.add.v2.f32 [%0], {%1,%2};"
                 :: "l"(addr), "f"(x), "f"(y) : "memory");
}
__device__ __forceinline__ void ldsm_x4(uint32_t* r, uint32_t addr) {
    asm volatile("ldmatrix.sync.aligned.m8n8.x4.shared.b16 {%0,%1,%2,%3}, [%4];"
                 : "=r"(r[0]), "=r"(r[1]), "=r"(r[2]), "=r"(r[3]) : "r"(addr));
}
__device__ __forceinline__ void mma_16816(float* c, const uint32_t* a, const uint32_t* b) {
    asm volatile("mma.sync.aligned.m16n8k16.row.col.f32.bf16.bf16.f32 "
                 "{%0,%1,%2,%3}, {%4,%5,%6,%7}, {%8,%9}, {%0,%1,%2,%3};"
                 : "+f"(c[0]), "+f"(c[1]), "+f"(c[2]), "+f"(c[3])
                 : "r"(a[0]), "r"(a[1]), "r"(a[2]), "r"(a[3]), "r"(b[0]), "r"(b[1]));
}
__device__ __forceinline__ void cp_async16(uint32_t s, const void* g, uint32_t sz) {
    asm volatile("cp.async.cg.shared.global [%0], [%1], 16, %2;"
                 :: "r"(s), "l"(g), "r"(sz) : "memory");
}
__device__ __forceinline__ uint32_t pack_hi(float x, float y, float& lx, float& ly) {
    __nv_bfloat16 h0 = __float2bfloat16_rn(x), h1 = __float2bfloat16_rn(y);
    lx = x - __bfloat162float(h0);
    ly = y - __bfloat162float(h1);
    __nv_bfloat162 hp(h0, h1);
    return *reinterpret_cast<uint32_t*>(&hp);
}
__device__ __forceinline__ uint32_t pack_bf2(float x, float y) {
    __nv_bfloat162 p = __floats2bfloat162_rn(x, y);
    return *reinterpret_cast<uint32_t*>(&p);
}

// ---------------- degree / scan / csr / buckets ----------------
__global__ void k_zero_deg() {
    int i = blockIdx.x * 256 + threadIdx.x;
    if (i < N_NODES) {
        g_deg[i] = 0; g_cur[i] = 0;
        *reinterpret_cast<float2*>(g_logit + i * 2) = make_float2(0.f, 0.f);
    }
    if (i < 64) g_meta[i] = 0;
}
__global__ void k_deg(const int* __restrict__ dst) {
    int e = blockIdx.x * 256 + threadIdx.x;
    if (e < N_EDGES) atomicAdd(&g_deg[dst[e]], 1);
}
__global__ void k_scan1() {
    __shared__ int s[256];
    int b = blockIdx.x, t = threadIdx.x, i = b * 256 + t;
    int v = (i < N_NODES) ? g_deg[i] : 0;
    s[t] = v;
    __syncthreads();
#pragma unroll
    for (int o = 1; o < 256; o <<= 1) {
        int u = (t >= o) ? s[t - o] : 0;
        __syncthreads();
        s[t] += u;
        __syncthreads();
    }
    if (i < N_NODES) {
        g_csr_off[i] = s[t] - v;
        atomicAdd(&g_meta[min(v, MAXDEG)], 1);
    }
    if (t == 255) g_bsum[b] = s[255];
}
__global__ void k_scan2() {
    __shared__ int s[1024];
    int t = threadIdx.x;
    if (t == 0) {
        int so = 0, ts = 0;
#pragma unroll
        for (int d = 0; d <= MAXDEG; d++) {
            int m = g_meta[d];
            g_meta[8 + d]  = so;  so += m;
            g_meta[24 + d] = ts;  ts += (m + 255) >> 8;
        }
        g_meta[30] = ts;
    }
    int v = (t < NBLK_SCAN) ? g_bsum[t] : 0;
    s[t] = v;
    __syncthreads();
#pragma unroll
    for (int o = 1; o < 1024; o <<= 1) {
        int u = (t >= o) ? s[t - o] : 0;
        __syncthreads();
        s[t] += u;
        __syncthreads();
    }
    if (t < NBLK_SCAN) g_bpre[t] = s[t] - v;
}
__global__ void k_scan3() {
    int i = blockIdx.x * 256 + threadIdx.x;
    if (i < N_NODES) g_csr_off[i] += g_bpre[i >> 8];
    if (i == 0) g_csr_off[N_NODES] = N_EDGES;
}
__global__ void k_fill_all(const int* __restrict__ src, const int* __restrict__ dst) {
    int t = blockIdx.x * 256 + threadIdx.x;
    if (t < N_EDGES) {
        int d = dst[t];
        int p = atomicAdd(&g_cur[d], 1);
        g_csr[g_csr_off[d] + p] = src[t];
    }
    if (t < N_NODES) {
        int dg = min(g_deg[t], MAXDEG);
        int p = atomicAdd(&g_meta[16 + dg], 1);
        g_perm[g_meta[8 + dg] + p] = t;
    }
}

// ---------------- CSR aggregation (fp32 input -> split bf16 msg), 2-way MLP ----------------
template <int CIN>
__global__ void k_agg(const float* __restrict__ hf,
                      __nv_bfloat16* __restrict__ mh, __nv_bfloat16* __restrict__ ml) {
    const int PER = CIN / 8;
    int t = blockIdx.x * 256 + threadIdx.x;
    int node = t / PER, g = t % PER;
    if (node >= N_NODES) return;
    int j0 = g_csr_off[node], j1 = g_csr_off[node + 1];
    float a[8];
#pragma unroll
    for (int i = 0; i < 8; i++) a[i] = 0.f;
    int j = j0;
    for (; j + 2 <= j1; j += 2) {
        int s0 = g_csr[j], s1 = g_csr[j + 1];
        const float4* p0 = reinterpret_cast<const float4*>(hf + (size_t)s0 * CIN + g * 8);
        const float4* p1 = reinterpret_cast<const float4*>(hf + (size_t)s1 * CIN + g * 8);
        float4 u0 = p0[0], u1 = p0[1];
        float4 v0 = p1[0], v1 = p1[1];
        a[0] += u0.x + v0.x; a[1] += u0.y + v0.y; a[2] += u0.z + v0.z; a[3] += u0.w + v0.w;
        a[4] += u1.x + v1.x; a[5] += u1.y + v1.y; a[6] += u1.z + v1.z; a[7] += u1.w + v1.w;
    }
    if (j < j1) {
        const float4* p0 = reinterpret_cast<const float4*>(hf + (size_t)g_csr[j] * CIN + g * 8);
        float4 u0 = p0[0], u1 = p0[1];
        a[0] += u0.x; a[1] += u0.y; a[2] += u0.z; a[3] += u0.w;
        a[4] += u1.x; a[5] += u1.y; a[6] += u1.z; a[7] += u1.w;
    }
    uint4 hw, lw;
    float l0, l1;
    hw.x = pack_hi(a[0], a[1], l0, l1); lw.x = pack_bf2(l0, l1);
    hw.y = pack_hi(a[2], a[3], l0, l1); lw.y = pack_bf2(l0, l1);
    hw.z = pack_hi(a[4], a[5], l0, l1); lw.z = pack_bf2(l0, l1);
    hw.w = pack_hi(a[6], a[7], l0, l1); lw.w = pack_bf2(l0, l1);
    *reinterpret_cast<uint4*>(mh + (size_t)node * CIN + g * 8) = hw;
    *reinterpret_cast<uint4*>(ml + (size_t)node * CIN + g * 8) = lw;
}

// ---------------- fused: x split + pool zero ----------------
__global__ void k_splitx_pool(const float* __restrict__ x,
                              __nv_bfloat16* __restrict__ xh, __nv_bfloat16* __restrict__ xl) {
    int t = blockIdx.x * 256 + threadIdx.x;
    if (t < N_GRAPHS * 64)
        reinterpret_cast<float4*>(g_pool)[t] = make_float4(0.f, 0.f, 0.f, 0.f);
    if (t >= N_NODES * 8) return;
    const float4* p = reinterpret_cast<const float4*>(x + (size_t)t * 8);
    float4 v0 = p[0], v1 = p[1];
    uint4 hw, lw;
    float l0, l1;
    hw.x = pack_hi(v0.x, v0.y, l0, l1); lw.x = pack_bf2(l0, l1);
    hw.y = pack_hi(v0.z, v0.w, l0, l1); lw.y = pack_bf2(l0, l1);
    hw.z = pack_hi(v1.x, v1.y, l0, l1); lw.z = pack_bf2(l0, l1);
    hw.w = pack_hi(v1.z, v1.w, l0, l1); lw.w = pack_bf2(l0, l1);
    *reinterpret_cast<uint4*>(xh + (size_t)t * 8) = hw;
    *reinterpret_cast<uint4*>(xl + (size_t)t * 8) = lw;
}

// ---------------- fused weight prep ----------------
__device__ __forceinline__ void prep_one(int t, int CIN, int COUT,
                                         const float* __restrict__ Wl, const float* __restrict__ Wr,
                                         __nv_bfloat16* __restrict__ Whi, __nv_bfloat16* __restrict__ Wlo) {
    int K = 2 * CIN;
    int n = t % COUT;
    int k = (t / COUT) % K;
    int d = t / (COUT * K);
    float v = (k < CIN) ? Wl[((size_t)d * CIN + k) * COUT + n]
                        : Wr[((size_t)d * CIN + (k - CIN)) * COUT + n];
    __nv_bfloat16 hi = __float2bfloat16_rn(v);
    float lo = v - __bfloat162float(hi);
    size_t o = ((size_t)(d * COUT + n)) * K + k;
    Whi[o] = hi;
    Wlo[o] = __float2bfloat16_rn(lo);
}
__global__ void k_prep_all(const float* __restrict__ Wl0, const float* __restrict__ Wr0,
                           const float* __restrict__ Wl1, const float* __restrict__ Wr1,
                           const float* __restrict__ Wl2, const float* __restrict__ Wr2,
                           const float* __restrict__ Wl3, const float* __restrict__ Wr3) {
    int t = blockIdx.x * 256 + threadIdx.x;
    if (t >= WTOT) return;
    if      (t < WOFF1) prep_one(t - WOFF0,  64, 128, Wl0, Wr0, g_whi + WOFF0, g_wlo + WOFF0);
    else if (t < WOFF2) prep_one(t - WOFF1, 128, 128, Wl1, Wr1, g_whi + WOFF1, g_wlo + WOFF1);
    else if (t < WOFF3) prep_one(t - WOFF2, 128, 256, Wl2, Wr2, g_whi + WOFF2, g_wlo + WOFF2);
    else                prep_one(t - WOFF3, 256, 256, Wl3, Wr3, g_whi + WOFF3, g_wlo + WOFF3);
}

// ---------------- pipelined mma.sync bucketed GEMM (256x128 tile, 64x64 warp tile) ----------------
// Non-POOL epilogue writes: split bf16 (next GEMM operand) + fp32 h (next agg input) + fused logit.
// POOL epilogue red-adds into g_pool + fused logit.
template <int CIN, int COUT, bool POOL>
__global__ __launch_bounds__(256, 1)
void mf_gemm(const __nv_bfloat16* __restrict__ hp_hi, const __nv_bfloat16* __restrict__ hp_lo,
             const __nv_bfloat16* __restrict__ Whi, const __nv_bfloat16* __restrict__ Wlo,
             const float* __restrict__ bl,
             const float* __restrict__ Wf, int loff,
             __nv_bfloat16* __restrict__ nx_hi, __nv_bfloat16* __restrict__ nx_lo,
             float* __restrict__ hf,
             float* __restrict__ logit,
             const int* __restrict__ batch, float* __restrict__ pool) {
    constexpr int K   = 2 * CIN;
    constexpr int NCH = K / 64;
    constexpr uint32_t STG = 98304;   // per-stage: A_hi 32K | A_lo 32K | B_hi 16K | B_lo 16K

    extern __shared__ char smem[];
    __shared__ int rows_s[256];
    __shared__ int bat_s[256];

    const int bx = blockIdx.x;
    if (bx >= g_meta[30]) return;
    int d = 0;
#pragma unroll
    for (int e = 1; e <= MAXDEG; e++)
        if (bx >= g_meta[24 + e]) d = e;
    const int tile = bx - g_meta[24 + d];
    const int slab = blockIdx.y;
    const int M    = g_meta[d];
    const int m0   = tile * 256;
    const int base = g_meta[8 + d];
    const int n0g  = slab * 128;
    const int tid  = threadIdx.x;
    const int lane = tid & 31, wid = tid >> 5;
    const int wm   = wid & 3, wn = wid >> 2;

    {
        int mi = m0 + tid;
        int nd = (mi < M) ? g_perm[base + mi] : -1;
        rows_s[tid] = nd;
        if (POOL) bat_s[tid] = (nd >= 0) ? batch[nd] : 0;
    }
    __syncthreads();

    const uint32_t sb = smem_u32(smem);

    auto load_chunk = [&](int c, int buf) {
        const __nv_bfloat16 *ah, *al;
        int kl;
        if (c * 64 < CIN) { ah = g_msg_hi; al = g_msg_lo; kl = c * 64; }
        else              { ah = hp_hi;    al = hp_lo;    kl = c * 64 - CIN; }
        uint32_t s0 = sb + buf * STG;
#pragma unroll
        for (int it = 0; it < 8; it++) {
            int idx = it * 256 + tid;
            int row = idx >> 3, seg = idx & 7;
            int node = rows_s[row];
            uint32_t doff = (uint32_t)(row * 128) + (uint32_t)((seg * 16) ^ ((row & 7) << 4));
            size_t go = (size_t)(node < 0 ? 0 : node) * CIN + kl + seg * 8;
            uint32_t sz = (node < 0) ? 0u : 16u;
            cp_async16(s0 + doff, ah + go, sz);
            cp_async16(s0 + 32768 + doff, al + go, sz);
        }
#pragma unroll
        for (int it = 0; it < 4; it++) {
            int idx = it * 256 + tid;
            int n = idx >> 3, seg = idx & 7;
            uint32_t doff = (uint32_t)(n * 128) + (uint32_t)((seg * 16) ^ ((n & 7) << 4));
            size_t go = ((size_t)(d * COUT + n0g + n)) * K + c * 64 + seg * 8;
            cp_async16(s0 + 65536 + doff, Whi + go, 16);
            cp_async16(s0 + 81920 + doff, Wlo + go, 16);
        }
        asm volatile("cp.async.commit_group;" ::: "memory");
    };

    float acc[4][8][4];
#pragma unroll
    for (int t = 0; t < 4; t++)
#pragma unroll
        for (int u = 0; u < 8; u++)
#pragma unroll
            for (int i = 0; i < 4; i++) acc[t][u][i] = 0.f;

    load_chunk(0, 0);

    for (int c = 0; c < NCH; c++) {
        if (c + 1 < NCH) {
            load_chunk(c + 1, (c + 1) & 1);
            asm volatile("cp.async.wait_group 1;" ::: "memory");
        } else {
            asm volatile("cp.async.wait_group 0;" ::: "memory");
        }
        __syncthreads();

        uint32_t s0 = sb + (uint32_t)(c & 1) * STG;
        uint32_t sAh = s0, sAl = s0 + 32768, sBh = s0 + 65536, sBl = s0 + 81920;
#pragma unroll
        for (int kk = 0; kk < 4; kk++) {
            uint32_t a_hi[4][4], a_lo[4][4];
            const int mrow = wm * 64 + (lane & 15);
            const int kseg = lane >> 4;
#pragma unroll
            for (int t = 0; t < 4; t++) {
                int row = mrow + t * 16;
                uint32_t off = (uint32_t)(row * 128) +
                               (uint32_t)((kk * 32 + kseg * 16) ^ ((row & 7) << 4));
                ldsm_x4(a_hi[t], sAh + off);
                ldsm_x4(a_lo[t], sAl + off);
            }
            const int bn = wn * 64 + ((lane >> 4) & 1) * 8 + (lane & 7);
            const int bk = kk * 32 + ((lane >> 3) & 1) * 16;
#pragma unroll
            for (int u2 = 0; u2 < 4; u2++) {
                int n = bn + u2 * 16;
                uint32_t off = (uint32_t)(n * 128) + (uint32_t)(bk ^ ((n & 7) << 4));
                uint32_t bh[4], blr[4];
                ldsm_x4(bh, sBh + off);
                ldsm_x4(blr, sBl + off);
#pragma unroll
                for (int t = 0; t < 4; t++) {
                    mma_16816(acc[t][u2 * 2 + 0], a_hi[t], bh + 0);
                    mma_16816(acc[t][u2 * 2 + 0], a_hi[t], blr + 0);
                    mma_16816(acc[t][u2 * 2 + 0], a_lo[t], bh + 0);
                    mma_16816(acc[t][u2 * 2 + 1], a_hi[t], bh + 2);
                    mma_16816(acc[t][u2 * 2 + 1], a_hi[t], blr + 2);
                    mma_16816(acc[t][u2 * 2 + 1], a_lo[t], bh + 2);
                }
            }
        }
        __syncthreads();
    }

    // ---- epilogue ----
    float lgA[4][2], lgB[4][2];
#pragma unroll
    for (int t = 0; t < 4; t++) { lgA[t][0] = lgA[t][1] = lgB[t][0] = lgB[t][1] = 0.f; }

#pragma unroll
    for (int t = 0; t < 4; t++) {
        int r0 = wm * 64 + t * 16 + (lane >> 2);
        int nd0 = rows_s[r0], nd1 = rows_s[r0 + 8];
        int b0 = POOL ? bat_s[r0] : 0, b1 = POOL ? bat_s[r0 + 8] : 0;
#pragma unroll
        for (int u = 0; u < 8; u++) {
            int col = n0g + wn * 64 + u * 8 + (lane & 3) * 2;
            float2 bv = *reinterpret_cast<const float2*>(bl + d * COUT + col);
            float4 wf = *reinterpret_cast<const float4*>(Wf + 2 * (loff + col));
            if (nd0 >= 0) {
                float ox = acc[t][u][0] + bv.x, oy = acc[t][u][1] + bv.y;
                if (POOL) {
                    red_add_v2(pool + (size_t)b0 * 256 + col, ox, oy);
                } else {
                    float lx, ly;
                    uint32_t hw = pack_hi(ox, oy, lx, ly);
                    *reinterpret_cast<uint32_t*>(nx_hi + (size_t)nd0 * COUT + col) = hw;
                    *reinterpret_cast<uint32_t*>(nx_lo + (size_t)nd0 * COUT + col) = pack_bf2(lx, ly);
                    *reinterpret_cast<float2*>(hf + (size_t)nd0 * COUT + col) = make_float2(ox, oy);
                }
                lgA[t][0] += ox * wf.x + oy * wf.z;
                lgB[t][0] += ox * wf.y + oy * wf.w;
            }
            if (nd1 >= 0) {
                float ox = acc[t][u][2] + bv.x, oy = acc[t][u][3] + bv.y;
                if (POOL) {
                    red_add_v2(pool + (size_t)b1 * 256 + col, ox, oy);
                } else {
                    float lx, ly;
                    uint32_t hw = pack_hi(ox, oy, lx, ly);
                    *reinterpret_cast<uint32_t*>(nx_hi + (size_t)nd1 * COUT + col) = hw;
                    *reinterpret_cast<uint32_t*>(nx_lo + (size_t)nd1 * COUT + col) = pack_bf2(lx, ly);
                    *reinterpret_cast<float2*>(hf + (size_t)nd1 * COUT + col) = make_float2(ox, oy);
                }
                lgA[t][1] += ox * wf.x + oy * wf.z;
                lgB[t][1] += ox * wf.y + oy * wf.w;
            }
        }
    }
#pragma unroll
    for (int t = 0; t < 4; t++)
#pragma unroll
        for (int r = 0; r < 2; r++) {
            float v0 = lgA[t][r], v1 = lgB[t][r];
            v0 += __shfl_xor_sync(0xFFFFFFFFu, v0, 1);
            v0 += __shfl_xor_sync(0xFFFFFFFFu, v0, 2);
            v1 += __shfl_xor_sync(0xFFFFFFFFu, v1, 1);
            v1 += __shfl_xor_sync(0xFFFFFFFFu, v1, 2);
            int rr = wm * 64 + t * 16 + (lane >> 2) + r * 8;
            int nd = rows_s[rr];
            if ((lane & 3) == 0 && nd >= 0) {
                atomicAdd(&logit[nd * 2 + 0], v0);
                atomicAdd(&logit[nd * 2 + 1], v1);
            }
        }
}

// ---------------- pooled-branch logits + finalize ----------------
__global__ void k_pool_dot(const float* __restrict__ Wf) {
    int gt = blockIdx.x * 256 + threadIdx.x;
    int g = gt >> 5, lane = gt & 31;
    if (g >= N_GRAPHS) return;
    float a0 = 0.f, a1 = 0.f;
#pragma unroll
    for (int k = lane; k < 256; k += 32) {
        float v = g_pool[(size_t)g * 256 + k];
        float2 w = *reinterpret_cast<const float2*>(Wf + 2 * (768 + k));
        a0 += v * w.x; a1 += v * w.y;
    }
#pragma unroll
    for (int o = 16; o > 0; o >>= 1) {
        a0 += __shfl_xor_sync(0xFFFFFFFFu, a0, o);
        a1 += __shfl_xor_sync(0xFFFFFFFFu, a1, o);
    }
    if (lane == 0) *reinterpret_cast<float2*>(g_glogit + g * 2) = make_float2(a0, a1);
}
__global__ void k_finalize(const int* __restrict__ batch, const float* __restrict__ bf,
                           float* __restrict__ out) {
    int i = blockIdx.x * 256 + threadIdx.x;
    if (i >= N_NODES) return;
    float2 nl = *reinterpret_cast<const float2*>(g_logit + i * 2);
    float2 gl = *reinterpret_cast<const float2*>(g_glogit + batch[i] * 2);
    float a0 = nl.x + gl.x + bf[0];
    float a1 = nl.y + gl.y + bf[1];
    float m  = fmaxf(a0, a1);
    float e0 = expf(a0 - m), e1 = expf(a1 - m);
    float s  = e0 + e1;
    *reinterpret_cast<float2*>(out + (size_t)i * 2) = make_float2(e0 / s, e1 / s);
}

// ---------------- launch ----------------
extern "C" void kernel_launch(void* const* d_in, const int* in_sizes, int n_in,
                              void* d_out, int out_size) {
    (void)in_sizes; (void)n_in; (void)out_size;
    const float* x     = (const float*)d_in[0];
    const int*   ei    = (const int*)d_in[1];
    const int*   batch = (const int*)d_in[2];
    const float* Wl0 = (const float*)d_in[3];
    const float* bl0 = (const float*)d_in[4];
    const float* Wr0 = (const float*)d_in[5];
    const float* Wl1 = (const float*)d_in[6];
    const float* bl1 = (const float*)d_in[7];
    const float* Wr1 = (const float*)d_in[8];
    const float* Wl2 = (const float*)d_in[9];
    const float* bl2 = (const float*)d_in[10];
    const float* Wr2 = (const float*)d_in[11];
    const float* Wl3 = (const float*)d_in[12];
    const float* bl3 = (const float*)d_in[13];
    const float* Wr3 = (const float*)d_in[14];
    const float* Wf  = (const float*)d_in[15];
    const float* bf  = (const float*)d_in[16];
    float* out = (float*)d_out;

    const int* src = ei;
    const int* dst = ei + N_EDGES;

    __nv_bfloat16 *whi, *wlo, *sah, *sal, *sbh, *sbl, *mh, *ml;
    float *lg, *pl, *hf;
    cudaGetSymbolAddress((void**)&whi, g_whi);
    cudaGetSymbolAddress((void**)&wlo, g_wlo);
    cudaGetSymbolAddress((void**)&sah, g_sa_hi);
    cudaGetSymbolAddress((void**)&sal, g_sa_lo);
    cudaGetSymbolAddress((void**)&sbh, g_sb_hi);
    cudaGetSymbolAddress((void**)&sbl, g_sb_lo);
    cudaGetSymbolAddress((void**)&mh, g_msg_hi);
    cudaGetSymbolAddress((void**)&ml, g_msg_lo);
    cudaGetSymbolAddress((void**)&lg, g_logit);
    cudaGetSymbolAddress((void**)&pl, g_pool);
    cudaGetSymbolAddress((void**)&hf, g_hf);

    const int SMEM = 196608;
    cudaFuncSetAttribute(mf_gemm<64, 128, false>,  cudaFuncAttributeMaxDynamicSharedMemorySize, SMEM);
    cudaFuncSetAttribute(mf_gemm<128, 128, false>, cudaFuncAttributeMaxDynamicSharedMemorySize, SMEM);
    cudaFuncSetAttribute(mf_gemm<128, 256, false>, cudaFuncAttributeMaxDynamicSharedMemorySize, SMEM);
    cudaFuncSetAttribute(mf_gemm<256, 256, true>,  cudaFuncAttributeMaxDynamicSharedMemorySize, SMEM);

    const int NB_N = (N_NODES + 255) / 256;
    const int NB_E = (N_EDGES + 255) / 256;

    // degree + CSR + buckets
    k_zero_deg<<<NB_N, 256>>>();
    k_deg<<<NB_E, 256>>>(dst);
    k_scan1<<<NBLK_SCAN, 256>>>();
    k_scan2<<<1, 1024>>>();
    k_scan3<<<NB_N, 256>>>();
    k_fill_all<<<NB_E, 256>>>(src, dst);

    // weight prep + x split + pool zero
    k_prep_all<<<(WTOT + 255) / 256, 256>>>(Wl0, Wr0, Wl1, Wr1, Wl2, Wr2, Wl3, Wr3);
    k_splitx_pool<<<(N_NODES * 8 + 255) / 256, 256>>>(x, sah, sal);

    // layer 0: 64 -> 128   (agg reads raw fp32 x; gemm in sa, out sb + hf)
    k_agg<64><<<(N_NODES * 8 + 255) / 256, 256>>>(x, mh, ml);
    mf_gemm<64, 128, false><<<dim3(MAX_TILES, 1), 256, SMEM>>>(sah, sal, whi + WOFF0, wlo + WOFF0, bl0, Wf, 0, sbh, sbl, hf, lg, nullptr, nullptr);

    // layer 1: 128 -> 128  (agg reads hf; gemm in sb, out sa + hf)
    k_agg<128><<<(N_NODES * 16 + 255) / 256, 256>>>(hf, mh, ml);
    mf_gemm<128, 128, false><<<dim3(MAX_TILES, 1), 256, SMEM>>>(sbh, sbl, whi + WOFF1, wlo + WOFF1, bl1, Wf, 128, sah, sal, hf, lg, nullptr, nullptr);

    // layer 2: 128 -> 256  (agg reads hf; gemm in sa, out sb + hf)
    k_agg<128><<<(N_NODES * 16 + 255) / 256, 256>>>(hf, mh, ml);
    mf_gemm<128, 256, false><<<dim3(MAX_TILES, 2), 256, SMEM>>>(sah, sal, whi + WOFF2, wlo + WOFF2, bl2, Wf, 256, sbh, sbl, hf, lg, nullptr, nullptr);

    // layer 3: 256 -> 256  (agg reads hf; pool-fused epilogue)
    k_agg<256><<<(N_NODES * 32 + 255) / 256, 256>>>(hf, mh, ml);
    mf_gemm<256, 256, true><<<dim3(MAX_TILES, 2), 256, SMEM>>>(sbh, sbl, whi + WOFF3, wlo + WOFF3, bl3, Wf, 512, nullptr, nullptr, nullptr, lg, batch, pl);

    // pooled-branch logits + softmax
    k_pool_dot<<<(N_GRAPHS * 32 + 255) / 256, 256>>>(Wf);
    k_finalize<<<NB_N, 256>>>(batch, bf, out);
}

// round 13
// speedup vs baseline: 1.0580x; 1.0580x over previous
#include <cuda_runtime.h>
#include <cuda_bf16.h>
#include <cstdint>

#define N_NODES  200000
#define N_EDGES  800000
#define N_GRAPHS 4096
#define MAXDEG   5
#define NBLK_SCAN 782   // ceil(N_NODES/256)
#define MAX_TILES 800   // ceil(N_NODES/256) + bucket remainders

// ---------------- scratch (static __device__, no allocs) ----------------
__device__ float g_pool[N_GRAPHS * 256];
__device__ float g_logit[N_NODES * 2];
__device__ float g_glogit[N_GRAPHS * 2];
__device__ __nv_bfloat16 g_msg_hi[N_NODES * 256];
__device__ __nv_bfloat16 g_msg_lo[N_NODES * 256];
__device__ __nv_bfloat16 g_sa_hi[N_NODES * 256];
__device__ __nv_bfloat16 g_sa_lo[N_NODES * 256];
__device__ __nv_bfloat16 g_sb_hi[N_NODES * 256];
__device__ __nv_bfloat16 g_sb_lo[N_NODES * 256];
__device__ int   g_deg[N_NODES];
__device__ int   g_cur[N_NODES];
__device__ int   g_perm[N_NODES];
__device__ int   g_csr_off[N_NODES + 1];
__device__ int   g_csr[N_EDGES];
__device__ int   g_bsum[1024];
__device__ int   g_bpre[1024];
// [0..5] counts, [8..13] offsets, [16..21] cursors, [24..29] tile starts, [30] total tiles
__device__ int   g_meta[64];

// split-bf16 transposed weights: [d][n][k] K-major (k spans 2*CIN: Wl then Wr)
#define WOFF0 0
#define WOFF1 98304
#define WOFF2 294912
#define WOFF3 688128
#define WTOT  1474560
__device__ __nv_bfloat16 g_whi[WTOT];
__device__ __nv_bfloat16 g_wlo[WTOT];

// ---------------- helpers (portable PTX only) ----------------
__device__ __forceinline__ uint32_t smem_u32(const void* p) {
    uint32_t a;
    asm("{ .reg .u64 t; cvta.to.shared.u64 t, %1; cvt.u32.u64 %0, t; }" : "=r"(a) : "l"(p));
    return a;
}
__device__ __forceinline__ void red_add_v2(float* addr, float x, float y) {
    asm volatile("red.global.add.v2.f32 [%0], {%1,%2};"
                 :: "l"(addr), "f"(x), "f"(y) : "memory");
}
__device__ __forceinline__ void ldsm_x4(uint32_t* r, uint32_t addr) {
    asm volatile("ldmatrix.sync.aligned.m8n8.x4.shared.b16 {%0,%1,%2,%3}, [%4];"
                 : "=r"(r[0]), "=r"(r[1]), "=r"(r[2]), "=r"(r[3]) : "r"(addr));
}
__device__ __forceinline__ void mma_16816(float* c, const uint32_t* a, const uint32_t* b) {
    asm volatile("mma.sync.aligned.m16n8k16.row.col.f32.bf16.bf16.f32 "
                 "{%0,%1,%2,%3}, {%4,%5,%6,%7}, {%8,%9}, {%0,%1,%2,%3};"
                 : "+f"(c[0]), "+f"(c[1]), "+f"(c[2]), "+f"(c[3])
                 : "r"(a[0]), "r"(a[1]), "r"(a[2]), "r"(a[3]), "r"(b[0]), "r"(b[1]));
}
__device__ __forceinline__ void cp_async16(uint32_t s, const void* g, uint32_t sz) {
    asm volatile("cp.async.cg.shared.global [%0], [%1], 16, %2;"
                 :: "r"(s), "l"(g), "r"(sz) : "memory");
}
__device__ __forceinline__ uint32_t pack_hi(float x, float y, float& lx, float& ly) {
    __nv_bfloat16 h0 = __float2bfloat16_rn(x), h1 = __float2bfloat16_rn(y);
    lx = x - __bfloat162float(h0);
    ly = y - __bfloat162float(h1);
    __nv_bfloat162 hp(h0, h1);
    return *reinterpret_cast<uint32_t*>(&hp);
}
__device__ __forceinline__ uint32_t pack_bf2(float x, float y) {
    __nv_bfloat162 p = __floats2bfloat162_rn(x, y);
    return *reinterpret_cast<uint32_t*>(&p);
}
__device__ __forceinline__ float2 upk(uint32_t u) {
    return __bfloat1622float2(*reinterpret_cast<__nv_bfloat162*>(&u));
}

// ---------------- degree / scan / csr / buckets ----------------
__global__ void k_zero_deg() {
    int i = blockIdx.x * 256 + threadIdx.x;
    if (i < N_NODES) {
        g_deg[i] = 0; g_cur[i] = 0;
        *reinterpret_cast<float2*>(g_logit + i * 2) = make_float2(0.f, 0.f);
    }
    if (i < 64) g_meta[i] = 0;
}
__global__ void k_deg(const int* __restrict__ dst) {
    int e = blockIdx.x * 256 + threadIdx.x;
    if (e < N_EDGES) atomicAdd(&g_deg[dst[e]], 1);
}
__global__ void k_scan1() {
    __shared__ int s[256];
    int b = blockIdx.x, t = threadIdx.x, i = b * 256 + t;
    int v = (i < N_NODES) ? g_deg[i] : 0;
    s[t] = v;
    __syncthreads();
#pragma unroll
    for (int o = 1; o < 256; o <<= 1) {
        int u = (t >= o) ? s[t - o] : 0;
        __syncthreads();
        s[t] += u;
        __syncthreads();
    }
    if (i < N_NODES) {
        g_csr_off[i] = s[t] - v;
        atomicAdd(&g_meta[min(v, MAXDEG)], 1);
    }
    if (t == 255) g_bsum[b] = s[255];
}
__global__ void k_scan2() {
    __shared__ int s[1024];
    int t = threadIdx.x;
    if (t == 0) {
        int so = 0, ts = 0;
#pragma unroll
        for (int d = 0; d <= MAXDEG; d++) {
            int m = g_meta[d];
            g_meta[8 + d]  = so;  so += m;
            g_meta[24 + d] = ts;  ts += (m + 255) >> 8;
        }
        g_meta[30] = ts;
    }
    int v = (t < NBLK_SCAN) ? g_bsum[t] : 0;
    s[t] = v;
    __syncthreads();
#pragma unroll
    for (int o = 1; o < 1024; o <<= 1) {
        int u = (t >= o) ? s[t - o] : 0;
        __syncthreads();
        s[t] += u;
        __syncthreads();
    }
    if (t < NBLK_SCAN) g_bpre[t] = s[t] - v;
}
__global__ void k_scan3() {
    int i = blockIdx.x * 256 + threadIdx.x;
    if (i < N_NODES) g_csr_off[i] += g_bpre[i >> 8];
    if (i == 0) g_csr_off[N_NODES] = N_EDGES;
}
__global__ void k_fill_all(const int* __restrict__ src, const int* __restrict__ dst) {
    int t = blockIdx.x * 256 + threadIdx.x;
    if (t < N_EDGES) {
        int d = dst[t];
        int p = atomicAdd(&g_cur[d], 1);
        g_csr[g_csr_off[d] + p] = src[t];
    }
    if (t < N_NODES) {
        int dg = min(g_deg[t], MAXDEG);
        int p = atomicAdd(&g_meta[16 + dg], 1);
        g_perm[g_meta[8 + dg] + p] = t;
    }
}

// ---------------- CSR aggregation (split in -> split msg), bucket-ordered, 2-way MLP ----------------
// Tasks indexed through g_perm so warps hold same-degree nodes (buckets 0..4): no
// divergence in the neighbor loop. Per-node arithmetic identical to natural order.
template <int CIN>
__global__ void k_agg(const __nv_bfloat16* __restrict__ hh, const __nv_bfloat16* __restrict__ hl,
                      __nv_bfloat16* __restrict__ mh, __nv_bfloat16* __restrict__ ml) {
    const int PER = CIN / 8;
    int t = blockIdx.x * 256 + threadIdx.x;
    int pos = t / PER, g = t % PER;
    if (pos >= N_NODES) return;
    int node = g_perm[pos];
    int j0 = g_csr_off[node], j1 = g_csr_off[node + 1];
    float a[8];
#pragma unroll
    for (int i = 0; i < 8; i++) a[i] = 0.f;
    int j = j0;
    for (; j + 2 <= j1; j += 2) {
        int s0 = g_csr[j], s1 = g_csr[j + 1];
        uint4 h0 = *reinterpret_cast<const uint4*>(hh + (size_t)s0 * CIN + g * 8);
        uint4 l0 = *reinterpret_cast<const uint4*>(hl + (size_t)s0 * CIN + g * 8);
        uint4 h1 = *reinterpret_cast<const uint4*>(hh + (size_t)s1 * CIN + g * 8);
        uint4 l1 = *reinterpret_cast<const uint4*>(hl + (size_t)s1 * CIN + g * 8);
        float2 p0 = upk(h0.x), p1 = upk(h0.y), p2 = upk(h0.z), p3 = upk(h0.w);
        float2 q0 = upk(l0.x), q1 = upk(l0.y), q2 = upk(l0.z), q3 = upk(l0.w);
        float2 r0 = upk(h1.x), r1 = upk(h1.y), r2 = upk(h1.z), r3 = upk(h1.w);
        float2 s0v = upk(l1.x), s1v = upk(l1.y), s2v = upk(l1.z), s3v = upk(l1.w);
        a[0] += (p0.x + q0.x) + (r0.x + s0v.x); a[1] += (p0.y + q0.y) + (r0.y + s0v.y);
        a[2] += (p1.x + q1.x) + (r1.x + s1v.x); a[3] += (p1.y + q1.y) + (r1.y + s1v.y);
        a[4] += (p2.x + q2.x) + (r2.x + s2v.x); a[5] += (p2.y + q2.y) + (r2.y + s2v.y);
        a[6] += (p3.x + q3.x) + (r3.x + s3v.x); a[7] += (p3.y + q3.y) + (r3.y + s3v.y);
    }
    if (j < j1) {
        int s0 = g_csr[j];
        uint4 hv = *reinterpret_cast<const uint4*>(hh + (size_t)s0 * CIN + g * 8);
        uint4 lv = *reinterpret_cast<const uint4*>(hl + (size_t)s0 * CIN + g * 8);
        float2 p0 = upk(hv.x), p1 = upk(hv.y), p2 = upk(hv.z), p3 = upk(hv.w);
        float2 q0 = upk(lv.x), q1 = upk(lv.y), q2 = upk(lv.z), q3 = upk(lv.w);
        a[0] += p0.x + q0.x; a[1] += p0.y + q0.y;
        a[2] += p1.x + q1.x; a[3] += p1.y + q1.y;
        a[4] += p2.x + q2.x; a[5] += p2.y + q2.y;
        a[6] += p3.x + q3.x; a[7] += p3.y + q3.y;
    }
    uint4 hw, lw;
    float l0, l1;
    hw.x = pack_hi(a[0], a[1], l0, l1); lw.x = pack_bf2(l0, l1);
    hw.y = pack_hi(a[2], a[3], l0, l1); lw.y = pack_bf2(l0, l1);
    hw.z = pack_hi(a[4], a[5], l0, l1); lw.z = pack_bf2(l0, l1);
    hw.w = pack_hi(a[6], a[7], l0, l1); lw.w = pack_bf2(l0, l1);
    *reinterpret_cast<uint4*>(mh + (size_t)node * CIN + g * 8) = hw;
    *reinterpret_cast<uint4*>(ml + (size_t)node * CIN + g * 8) = lw;
}

// ---------------- fused: x split + pool zero ----------------
__global__ void k_splitx_pool(const float* __restrict__ x,
                              __nv_bfloat16* __restrict__ xh, __nv_bfloat16* __restrict__ xl) {
    int t = blockIdx.x * 256 + threadIdx.x;
    if (t < N_GRAPHS * 64)
        reinterpret_cast<float4*>(g_pool)[t] = make_float4(0.f, 0.f, 0.f, 0.f);
    if (t >= N_NODES * 8) return;
    const float4* p = reinterpret_cast<const float4*>(x + (size_t)t * 8);
    float4 v0 = p[0], v1 = p[1];
    uint4 hw, lw;
    float l0, l1;
    hw.x = pack_hi(v0.x, v0.y, l0, l1); lw.x = pack_bf2(l0, l1);
    hw.y = pack_hi(v0.z, v0.w, l0, l1); lw.y = pack_bf2(l0, l1);
    hw.z = pack_hi(v1.x, v1.y, l0, l1); lw.z = pack_bf2(l0, l1);
    hw.w = pack_hi(v1.z, v1.w, l0, l1); lw.w = pack_bf2(l0, l1);
    *reinterpret_cast<uint4*>(xh + (size_t)t * 8) = hw;
    *reinterpret_cast<uint4*>(xl + (size_t)t * 8) = lw;
}

// ---------------- fused weight prep ----------------
__device__ __forceinline__ void prep_one(int t, int CIN, int COUT,
                                         const float* __restrict__ Wl, const float* __restrict__ Wr,
                                         __nv_bfloat16* __restrict__ Whi, __nv_bfloat16* __restrict__ Wlo) {
    int K = 2 * CIN;
    int n = t % COUT;
    int k = (t / COUT) % K;
    int d = t / (COUT * K);
    float v = (k < CIN) ? Wl[((size_t)d * CIN + k) * COUT + n]
                        : Wr[((size_t)d * CIN + (k - CIN)) * COUT + n];
    __nv_bfloat16 hi = __float2bfloat16_rn(v);
    float lo = v - __bfloat162float(hi);
    size_t o = ((size_t)(d * COUT + n)) * K + k;
    Whi[o] = hi;
    Wlo[o] = __float2bfloat16_rn(lo);
}
__global__ void k_prep_all(const float* __restrict__ Wl0, const float* __restrict__ Wr0,
                           const float* __restrict__ Wl1, const float* __restrict__ Wr1,
                           const float* __restrict__ Wl2, const float* __restrict__ Wr2,
                           const float* __restrict__ Wl3, const float* __restrict__ Wr3) {
    int t = blockIdx.x * 256 + threadIdx.x;
    if (t >= WTOT) return;
    if      (t < WOFF1) prep_one(t - WOFF0,  64, 128, Wl0, Wr0, g_whi + WOFF0, g_wlo + WOFF0);
    else if (t < WOFF2) prep_one(t - WOFF1, 128, 128, Wl1, Wr1, g_whi + WOFF1, g_wlo + WOFF1);
    else if (t < WOFF3) prep_one(t - WOFF2, 128, 256, Wl2, Wr2, g_whi + WOFF2, g_wlo + WOFF2);
    else                prep_one(t - WOFF3, 256, 256, Wl3, Wr3, g_whi + WOFF3, g_wlo + WOFF3);
}

// ---------------- pipelined mma.sync bucketed GEMM (256x128 tile, 64x64 warp tile) ----------------
template <int CIN, int COUT, bool POOL>
__global__ __launch_bounds__(256, 1)
void mf_gemm(const __nv_bfloat16* __restrict__ hp_hi, const __nv_bfloat16* __restrict__ hp_lo,
             const __nv_bfloat16* __restrict__ Whi, const __nv_bfloat16* __restrict__ Wlo,
             const float* __restrict__ bl,
             const float* __restrict__ Wf, int loff,
             __nv_bfloat16* __restrict__ nx_hi, __nv_bfloat16* __restrict__ nx_lo,
             float* __restrict__ logit,
             const int* __restrict__ batch, float* __restrict__ pool) {
    constexpr int K   = 2 * CIN;
    constexpr int NCH = K / 64;
    constexpr uint32_t STG = 98304;   // per-stage: A_hi 32K | A_lo 32K | B_hi 16K | B_lo 16K

    extern __shared__ char smem[];
    __shared__ int rows_s[256];
    __shared__ int bat_s[256];

    const int bx = blockIdx.x;
    if (bx >= g_meta[30]) return;
    int d = 0;
#pragma unroll
    for (int e = 1; e <= MAXDEG; e++)
        if (bx >= g_meta[24 + e]) d = e;
    const int tile = bx - g_meta[24 + d];
    const int slab = blockIdx.y;
    const int M    = g_meta[d];
    const int m0   = tile * 256;
    const int base = g_meta[8 + d];
    const int n0g  = slab * 128;
    const int tid  = threadIdx.x;
    const int lane = tid & 31, wid = tid >> 5;
    const int wm   = wid & 3, wn = wid >> 2;

    {
        int mi = m0 + tid;
        int nd = (mi < M) ? g_perm[base + mi] : -1;
        rows_s[tid] = nd;
        if (POOL) bat_s[tid] = (nd >= 0) ? batch[nd] : 0;
    }
    __syncthreads();

    const uint32_t sb = smem_u32(smem);

    auto load_chunk = [&](int c, int buf) {
        const __nv_bfloat16 *ah, *al;
        int kl;
        if (c * 64 < CIN) { ah = g_msg_hi; al = g_msg_lo; kl = c * 64; }
        else              { ah = hp_hi;    al = hp_lo;    kl = c * 64 - CIN; }
        uint32_t s0 = sb + buf * STG;
#pragma unroll
        for (int it = 0; it < 8; it++) {
            int idx = it * 256 + tid;
            int row = idx >> 3, seg = idx & 7;
            int node = rows_s[row];
            uint32_t doff = (uint32_t)(row * 128) + (uint32_t)((seg * 16) ^ ((row & 7) << 4));
            size_t go = (size_t)(node < 0 ? 0 : node) * CIN + kl + seg * 8;
            uint32_t sz = (node < 0) ? 0u : 16u;
            cp_async16(s0 + doff, ah + go, sz);
            cp_async16(s0 + 32768 + doff, al + go, sz);
        }
#pragma unroll
        for (int it = 0; it < 4; it++) {
            int idx = it * 256 + tid;
            int n = idx >> 3, seg = idx & 7;
            uint32_t doff = (uint32_t)(n * 128) + (uint32_t)((seg * 16) ^ ((n & 7) << 4));
            size_t go = ((size_t)(d * COUT + n0g + n)) * K + c * 64 + seg * 8;
            cp_async16(s0 + 65536 + doff, Whi + go, 16);
            cp_async16(s0 + 81920 + doff, Wlo + go, 16);
        }
        asm volatile("cp.async.commit_group;" ::: "memory");
    };

    float acc[4][8][4];
#pragma unroll
    for (int t = 0; t < 4; t++)
#pragma unroll
        for (int u = 0; u < 8; u++)
#pragma unroll
            for (int i = 0; i < 4; i++) acc[t][u][i] = 0.f;

    load_chunk(0, 0);

    for (int c = 0; c < NCH; c++) {
        if (c + 1 < NCH) {
            load_chunk(c + 1, (c + 1) & 1);
            asm volatile("cp.async.wait_group 1;" ::: "memory");
        } else {
            asm volatile("cp.async.wait_group 0;" ::: "memory");
        }
        __syncthreads();

        uint32_t s0 = sb + (uint32_t)(c & 1) * STG;
        uint32_t sAh = s0, sAl = s0 + 32768, sBh = s0 + 65536, sBl = s0 + 81920;
#pragma unroll
        for (int kk = 0; kk < 4; kk++) {
            uint32_t a_hi[4][4], a_lo[4][4];
            const int mrow = wm * 64 + (lane & 15);
            const int kseg = lane >> 4;
#pragma unroll
            for (int t = 0; t < 4; t++) {
                int row = mrow + t * 16;
                uint32_t off = (uint32_t)(row * 128) +
                               (uint32_t)((kk * 32 + kseg * 16) ^ ((row & 7) << 4));
                ldsm_x4(a_hi[t], sAh + off);
                ldsm_x4(a_lo[t], sAl + off);
            }
            const int bn = wn * 64 + ((lane >> 4) & 1) * 8 + (lane & 7);
            const int bk = kk * 32 + ((lane >> 3) & 1) * 16;
#pragma unroll
            for (int u2 = 0; u2 < 4; u2++) {
                int n = bn + u2 * 16;
                uint32_t off = (uint32_t)(n * 128) + (uint32_t)(bk ^ ((n & 7) << 4));
                uint32_t bh[4], blr[4];
                ldsm_x4(bh, sBh + off);
                ldsm_x4(blr, sBl + off);
#pragma unroll
                for (int t = 0; t < 4; t++) {
                    mma_16816(acc[t][u2 * 2 + 0], a_hi[t], bh + 0);
                    mma_16816(acc[t][u2 * 2 + 0], a_hi[t], blr + 0);
                    mma_16816(acc[t][u2 * 2 + 0], a_lo[t], bh + 0);
                    mma_16816(acc[t][u2 * 2 + 1], a_hi[t], bh + 2);
                    mma_16816(acc[t][u2 * 2 + 1], a_hi[t], blr + 2);
                    mma_16816(acc[t][u2 * 2 + 1], a_lo[t], bh + 2);
                }
            }
        }
        __syncthreads();
    }

    // ---- epilogue: bias + (split bf16 out | pool red-add) + fused logit dot ----
    float lgA[4][2], lgB[4][2];
#pragma unroll
    for (int t = 0; t < 4; t++) { lgA[t][0] = lgA[t][1] = lgB[t][0] = lgB[t][1] = 0.f; }

#pragma unroll
    for (int t = 0; t < 4; t++) {
        int r0 = wm * 64 + t * 16 + (lane >> 2);
        int nd0 = rows_s[r0], nd1 = rows_s[r0 + 8];
        int b0 = POOL ? bat_s[r0] : 0, b1 = POOL ? bat_s[r0 + 8] : 0;
#pragma unroll
        for (int u = 0; u < 8; u++) {
            int col = n0g + wn * 64 + u * 8 + (lane & 3) * 2;
            float2 bv = *reinterpret_cast<const float2*>(bl + d * COUT + col);
            float4 wf = *reinterpret_cast<const float4*>(Wf + 2 * (loff + col));
            if (nd0 >= 0) {
                float ox = acc[t][u][0] + bv.x, oy = acc[t][u][1] + bv.y;
                if (POOL) {
                    red_add_v2(pool + (size_t)b0 * 256 + col, ox, oy);
                } else {
                    float lx, ly;
                    uint32_t hw = pack_hi(ox, oy, lx, ly);
                    *reinterpret_cast<uint32_t*>(nx_hi + (size_t)nd0 * COUT + col) = hw;
                    *reinterpret_cast<uint32_t*>(nx_lo + (size_t)nd0 * COUT + col) = pack_bf2(lx, ly);
                }
                lgA[t][0] += ox * wf.x + oy * wf.z;
                lgB[t][0] += ox * wf.y + oy * wf.w;
            }
            if (nd1 >= 0) {
                float ox = acc[t][u][2] + bv.x, oy = acc[t][u][3] + bv.y;
                if (POOL) {
                    red_add_v2(pool + (size_t)b1 * 256 + col, ox, oy);
                } else {
                    float lx, ly;
                    uint32_t hw = pack_hi(ox, oy, lx, ly);
                    *reinterpret_cast<uint32_t*>(nx_hi + (size_t)nd1 * COUT + col) = hw;
                    *reinterpret_cast<uint32_t*>(nx_lo + (size_t)nd1 * COUT + col) = pack_bf2(lx, ly);
                }
                lgA[t][1] += ox * wf.x + oy * wf.z;
                lgB[t][1] += ox * wf.y + oy * wf.w;
            }
        }
    }
#pragma unroll
    for (int t = 0; t < 4; t++)
#pragma unroll
        for (int r = 0; r < 2; r++) {
            float v0 = lgA[t][r], v1 = lgB[t][r];
            v0 += __shfl_xor_sync(0xFFFFFFFFu, v0, 1);
            v0 += __shfl_xor_sync(0xFFFFFFFFu, v0, 2);
            v1 += __shfl_xor_sync(0xFFFFFFFFu, v1, 1);
            v1 += __shfl_xor_sync(0xFFFFFFFFu, v1, 2);
            int rr = wm * 64 + t * 16 + (lane >> 2) + r * 8;
            int nd = rows_s[rr];
            if ((lane & 3) == 0 && nd >= 0) {
                atomicAdd(&logit[nd * 2 + 0], v0);
                atomicAdd(&logit[nd * 2 + 1], v1);
            }
        }
}

// ---------------- pooled-branch logits + finalize ----------------
__global__ void k_pool_dot(const float* __restrict__ Wf) {
    int gt = blockIdx.x * 256 + threadIdx.x;
    int g = gt >> 5, lane = gt & 31;
    if (g >= N_GRAPHS) return;
    float a0 = 0.f, a1 = 0.f;
#pragma unroll
    for (int k = lane; k < 256; k += 32) {
        float v = g_pool[(size_t)g * 256 + k];
        float2 w = *reinterpret_cast<const float2*>(Wf + 2 * (768 + k));
        a0 += v * w.x; a1 += v * w.y;
    }
#pragma unroll
    for (int o = 16; o > 0; o >>= 1) {
        a0 += __shfl_xor_sync(0xFFFFFFFFu, a0, o);
        a1 += __shfl_xor_sync(0xFFFFFFFFu, a1, o);
    }
    if (lane == 0) *reinterpret_cast<float2*>(g_glogit + g * 2) = make_float2(a0, a1);
}
__global__ void k_finalize(const int* __restrict__ batch, const float* __restrict__ bf,
                           float* __restrict__ out) {
    int i = blockIdx.x * 256 + threadIdx.x;
    if (i >= N_NODES) return;
    float2 nl = *reinterpret_cast<const float2*>(g_logit + i * 2);
    float2 gl = *reinterpret_cast<const float2*>(g_glogit + batch[i] * 2);
    float a0 = nl.x + gl.x + bf[0];
    float a1 = nl.y + gl.y + bf[1];
    float m  = fmaxf(a0, a1);
    float e0 = expf(a0 - m), e1 = expf(a1 - m);
    float s  = e0 + e1;
    *reinterpret_cast<float2*>(out + (size_t)i * 2) = make_float2(e0 / s, e1 / s);
}

// ---------------- launch ----------------
extern "C" void kernel_launch(void* const* d_in, const int* in_sizes, int n_in,
                              void* d_out, int out_size) {
    (void)in_sizes; (void)n_in; (void)out_size;
    const float* x     = (const float*)d_in[0];
    const int*   ei    = (const int*)d_in[1];
    const int*   batch = (const int*)d_in[2];
    const float* Wl0 = (const float*)d_in[3];
    const float* bl0 = (const float*)d_in[4];
    const float* Wr0 = (const float*)d_in[5];
    const float* Wl1 = (const float*)d_in[6];
    const float* bl1 = (const float*)d_in[7];
    const float* Wr1 = (const float*)d_in[8];
    const float* Wl2 = (const float*)d_in[9];
    const float* bl2 = (const float*)d_in[10];
    const float* Wr2 = (const float*)d_in[11];
    const float* Wl3 = (const float*)d_in[12];
    const float* bl3 = (const float*)d_in[13];
    const float* Wr3 = (const float*)d_in[14];
    const float* Wf  = (const float*)d_in[15];
    const float* bf  = (const float*)d_in[16];
    float* out = (float*)d_out;

    const int* src = ei;
    const int* dst = ei + N_EDGES;

    __nv_bfloat16 *whi, *wlo, *sah, *sal, *sbh, *sbl, *mh, *ml;
    float *lg, *pl;
    cudaGetSymbolAddress((void**)&whi, g_whi);
    cudaGetSymbolAddress((void**)&wlo, g_wlo);
    cudaGetSymbolAddress((void**)&sah, g_sa_hi);
    cudaGetSymbolAddress((void**)&sal, g_sa_lo);
    cudaGetSymbolAddress((void**)&sbh, g_sb_hi);
    cudaGetSymbolAddress((void**)&sbl, g_sb_lo);
    cudaGetSymbolAddress((void**)&mh, g_msg_hi);
    cudaGetSymbolAddress((void**)&ml, g_msg_lo);
    cudaGetSymbolAddress((void**)&lg, g_logit);
    cudaGetSymbolAddress((void**)&pl, g_pool);

    const int SMEM = 196608;
    cudaFuncSetAttribute(mf_gemm<64, 128, false>,  cudaFuncAttributeMaxDynamicSharedMemorySize, SMEM);
    cudaFuncSetAttribute(mf_gemm<128, 128, false>, cudaFuncAttributeMaxDynamicSharedMemorySize, SMEM);
    cudaFuncSetAttribute(mf_gemm<128, 256, false>, cudaFuncAttributeMaxDynamicSharedMemorySize, SMEM);
    cudaFuncSetAttribute(mf_gemm<256, 256, true>,  cudaFuncAttributeMaxDynamicSharedMemorySize, SMEM);

    const int NB_N = (N_NODES + 255) / 256;
    const int NB_E = (N_EDGES + 255) / 256;

    // degree + CSR + buckets
    k_zero_deg<<<NB_N, 256>>>();
    k_deg<<<NB_E, 256>>>(dst);
    k_scan1<<<NBLK_SCAN, 256>>>();
    k_scan2<<<1, 1024>>>();
    k_scan3<<<NB_N, 256>>>();
    k_fill_all<<<NB_E, 256>>>(src, dst);

    // weight prep + x split + pool zero
    k_prep_all<<<(WTOT + 255) / 256, 256>>>(Wl0, Wr0, Wl1, Wr1, Wl2, Wr2, Wl3, Wr3);
    k_splitx_pool<<<(N_NODES * 8 + 255) / 256, 256>>>(x, sah, sal);

    // layer 0: 64 -> 128   (in sa, out sb)
    k_agg<64><<<(N_NODES * 8 + 255) / 256, 256>>>(sah, sal, mh, ml);
    mf_gemm<64, 128, false><<<dim3(MAX_TILES, 1), 256, SMEM>>>(sah, sal, whi + WOFF0, wlo + WOFF0, bl0, Wf, 0, sbh, sbl, lg, nullptr, nullptr);

    // layer 1: 128 -> 128  (in sb, out sa)
    k_agg<128><<<(N_NODES * 16 + 255) / 256, 256>>>(sbh, sbl, mh, ml);
    mf_gemm<128, 128, false><<<dim3(MAX_TILES, 1), 256, SMEM>>>(sbh, sbl, whi + WOFF1, wlo + WOFF1, bl1, Wf, 128, sah, sal, lg, nullptr, nullptr);

    // layer 2: 128 -> 256  (in sa, out sb)
    k_agg<128><<<(N_NODES * 16 + 255) / 256, 256>>>(sah, sal, mh, ml);
    mf_gemm<128, 256, false><<<dim3(MAX_TILES, 2), 256, SMEM>>>(sah, sal, whi + WOFF2, wlo + WOFF2, bl2, Wf, 256, sbh, sbl, lg, nullptr, nullptr);

    // layer 3: 256 -> 256  (in sb; pool-fused epilogue, no hidden-state store)
    k_agg<256><<<(N_NODES * 32 + 255) / 256, 256>>>(sbh, sbl, mh, ml);
    mf_gemm<256, 256, true><<<dim3(MAX_TILES, 2), 256, SMEM>>>(sbh, sbl, whi + WOFF3, wlo + WOFF3, bl3, Wf, 512, nullptr, nullptr, lg, batch, pl);

    // pooled-branch logits + softmax
    k_pool_dot<<<(N_GRAPHS * 32 + 255) / 256, 256>>>(Wf);
    k_finalize<<<NB_N, 256>>>(batch, bf, out);
}